// round 9
// baseline (speedup 1.0000x reference)
#include <cuda_runtime.h>

#define TOKENS 8192
#define INDIM  256
#define MDIM   512
#define QKV3   1536
#define NHEADS 8
#define DHEAD  64
#define NSEQ   2048
#define CATD   768
#define SCALE  0.125f

// ---------------- scratch (device globals; no allocations allowed) --------
__device__ float g_qkv [TOKENS * QKV3];   // 50.3 MB
__device__ float g_attn[TOKENS * MDIM];   // 16.8 MB
__device__ float g_cat [TOKENS * CATD];   // 25.2 MB

// ---------------- generic tiled fp32 GEMM: C = A @ B + bias ---------------
// A: [M,K] row-major (lda), B: [K,N] row-major (ldb), C: [M,N] (ldc)
// BM=BN=64, BK=16, 256 threads, 4x4 per thread.
__global__ __launch_bounds__(256) void gemm_bias(
    const float* __restrict__ A, int lda,
    const float* __restrict__ B, int ldb,
    const float* __restrict__ bias,
    float* __restrict__ C, int ldc,
    int M, int N, int K)
{
    __shared__ float As[16][65];   // transposed: As[k][m], padded
    __shared__ float Bs[16][64];   // Bs[k][n]

    const int tid = threadIdx.x;
    const int tr  = tid >> 4;      // 0..15 -> output rows tr*4..tr*4+3
    const int tc  = tid & 15;      // 0..15 -> output cols tc*4..tc*4+3
    const int m0  = blockIdx.y * 64;
    const int n0  = blockIdx.x * 64;

    // A tile load: 64 rows x 16 cols, one float4 per thread
    const int a_row = tid >> 2;          // 0..63
    const int a_col = (tid & 3) * 4;     // 0,4,8,12
    // B tile load: 16 rows x 64 cols, one float4 per thread
    const int b_row = tid >> 4;          // 0..15
    const int b_col = (tid & 15) * 4;    // 0..60

    const float* Aptr = A + (size_t)(m0 + a_row) * lda + a_col;
    const float* Bptr = B + (size_t)b_row * ldb + n0 + b_col;

    float acc[4][4];
#pragma unroll
    for (int i = 0; i < 4; i++)
#pragma unroll
        for (int j = 0; j < 4; j++) acc[i][j] = 0.f;

    for (int k0 = 0; k0 < K; k0 += 16) {
        float4 av = *(const float4*)(Aptr + k0);
        float4 bv = *(const float4*)(Bptr + (size_t)k0 * ldb);
        As[a_col + 0][a_row] = av.x;
        As[a_col + 1][a_row] = av.y;
        As[a_col + 2][a_row] = av.z;
        As[a_col + 3][a_row] = av.w;
        *(float4*)&Bs[b_row][b_col] = bv;
        __syncthreads();

#pragma unroll
        for (int kk = 0; kk < 16; kk++) {
            float a0 = As[kk][tr * 4 + 0];
            float a1 = As[kk][tr * 4 + 1];
            float a2 = As[kk][tr * 4 + 2];
            float a3 = As[kk][tr * 4 + 3];
            float4 b4 = *(const float4*)&Bs[kk][tc * 4];
            acc[0][0] += a0 * b4.x; acc[0][1] += a0 * b4.y; acc[0][2] += a0 * b4.z; acc[0][3] += a0 * b4.w;
            acc[1][0] += a1 * b4.x; acc[1][1] += a1 * b4.y; acc[1][2] += a1 * b4.z; acc[1][3] += a1 * b4.w;
            acc[2][0] += a2 * b4.x; acc[2][1] += a2 * b4.y; acc[2][2] += a2 * b4.z; acc[2][3] += a2 * b4.w;
            acc[3][0] += a3 * b4.x; acc[3][1] += a3 * b4.y; acc[3][2] += a3 * b4.z; acc[3][3] += a3 * b4.w;
        }
        __syncthreads();
    }

    const float bx = bias[n0 + tc * 4 + 0];
    const float by = bias[n0 + tc * 4 + 1];
    const float bz = bias[n0 + tc * 4 + 2];
    const float bw = bias[n0 + tc * 4 + 3];
#pragma unroll
    for (int i = 0; i < 4; i++) {
        float4 o;
        o.x = acc[i][0] + bx;
        o.y = acc[i][1] + by;
        o.z = acc[i][2] + bz;
        o.w = acc[i][3] + bw;
        *(float4*)&C[(size_t)(m0 + tr * 4 + i) * ldc + n0 + tc * 4] = o;
    }
}

// ---------------- flash attention (fp32, 64x64 tiles) ---------------------
// qkv row layout: [ q(512) | k(512) | v(512) ], head h at col h*64.
// grid: (NSEQ/64, NHEADS, B), 256 threads. Online softmax.
__global__ __launch_bounds__(256) void attn_kernel(
    const float* __restrict__ qkv, float* __restrict__ outp)
{
    extern __shared__ float sm[];
    float* Qs = sm;                 // [64][65]
    float* KP = sm + 64 * 65;       // K tile, then reused as P tile [64][65]
    float* Vs = sm + 2 * 64 * 65;   // [64][65]

    const int tid = threadIdx.x;
    const int tr  = tid >> 4;       // rows tr*4..+3
    const int tc  = tid & 15;       // cols tc*4..+3
    const int q0  = blockIdx.x * 64;
    const int h   = blockIdx.y;
    const int b   = blockIdx.z;
    const size_t rowbase = (size_t)b * NSEQ;

    // ---- load Q tile [64 x 64] ----
    const float* qptr = qkv + (rowbase + q0) * QKV3 + h * DHEAD;
#pragma unroll
    for (int u = 0; u < 4; u++) {
        int idx = tid + u * 256;
        int r = idx >> 4, c = (idx & 15) * 4;
        float4 v = *(const float4*)(qptr + (size_t)r * QKV3 + c);
        Qs[r * 65 + c + 0] = v.x; Qs[r * 65 + c + 1] = v.y;
        Qs[r * 65 + c + 2] = v.z; Qs[r * 65 + c + 3] = v.w;
    }

    float m[4], l[4], acc[4][4];
#pragma unroll
    for (int i = 0; i < 4; i++) {
        m[i] = -1e30f; l[i] = 0.f;
#pragma unroll
        for (int j = 0; j < 4; j++) acc[i][j] = 0.f;
    }
    __syncthreads();

    for (int t = 0; t < NSEQ; t += 64) {
        // ---- load K and V tiles ----
        const float* kptr = qkv + (rowbase + t) * QKV3 + MDIM + h * DHEAD;
        const float* vptr = qkv + (rowbase + t) * QKV3 + 2 * MDIM + h * DHEAD;
#pragma unroll
        for (int u = 0; u < 4; u++) {
            int idx = tid + u * 256;
            int r = idx >> 4, c = (idx & 15) * 4;
            float4 kv4 = *(const float4*)(kptr + (size_t)r * QKV3 + c);
            KP[r * 65 + c + 0] = kv4.x; KP[r * 65 + c + 1] = kv4.y;
            KP[r * 65 + c + 2] = kv4.z; KP[r * 65 + c + 3] = kv4.w;
            float4 vv4 = *(const float4*)(vptr + (size_t)r * QKV3 + c);
            Vs[r * 65 + c + 0] = vv4.x; Vs[r * 65 + c + 1] = vv4.y;
            Vs[r * 65 + c + 2] = vv4.z; Vs[r * 65 + c + 3] = vv4.w;
        }
        __syncthreads();

        // ---- S = Q @ K^T (4x4 per thread) ----
        float s[4][4];
#pragma unroll
        for (int i = 0; i < 4; i++)
#pragma unroll
            for (int j = 0; j < 4; j++) s[i][j] = 0.f;

#pragma unroll 8
        for (int d = 0; d < 64; d++) {
            float a0 = Qs[(tr * 4 + 0) * 65 + d];
            float a1 = Qs[(tr * 4 + 1) * 65 + d];
            float a2 = Qs[(tr * 4 + 2) * 65 + d];
            float a3 = Qs[(tr * 4 + 3) * 65 + d];
            float b0 = KP[(tc * 4 + 0) * 65 + d];
            float b1 = KP[(tc * 4 + 1) * 65 + d];
            float b2 = KP[(tc * 4 + 2) * 65 + d];
            float b3 = KP[(tc * 4 + 3) * 65 + d];
            s[0][0] += a0 * b0; s[0][1] += a0 * b1; s[0][2] += a0 * b2; s[0][3] += a0 * b3;
            s[1][0] += a1 * b0; s[1][1] += a1 * b1; s[1][2] += a1 * b2; s[1][3] += a1 * b3;
            s[2][0] += a2 * b0; s[2][1] += a2 * b1; s[2][2] += a2 * b2; s[2][3] += a2 * b3;
            s[3][0] += a3 * b0; s[3][1] += a3 * b1; s[3][2] += a3 * b2; s[3][3] += a3 * b3;
        }

        // ---- online softmax over rows (16 lanes share one row group) ----
#pragma unroll
        for (int i = 0; i < 4; i++) {
#pragma unroll
            for (int j = 0; j < 4; j++) s[i][j] *= SCALE;
            float tm = fmaxf(fmaxf(s[i][0], s[i][1]), fmaxf(s[i][2], s[i][3]));
#pragma unroll
            for (int off = 8; off > 0; off >>= 1)
                tm = fmaxf(tm, __shfl_xor_sync(0xffffffffu, tm, off));
            float mn = fmaxf(m[i], tm);
            float al = __expf(m[i] - mn);
            float rs = 0.f;
#pragma unroll
            for (int j = 0; j < 4; j++) {
                s[i][j] = __expf(s[i][j] - mn);
                rs += s[i][j];
            }
#pragma unroll
            for (int off = 8; off > 0; off >>= 1)
                rs += __shfl_xor_sync(0xffffffffu, rs, off);
            l[i] = l[i] * al + rs;
#pragma unroll
            for (int j = 0; j < 4; j++) acc[i][j] *= al;
            m[i] = mn;
        }

        __syncthreads();   // all K reads done before overwriting with P
#pragma unroll
        for (int i = 0; i < 4; i++)
#pragma unroll
            for (int j = 0; j < 4; j++)
                KP[(tr * 4 + i) * 65 + tc * 4 + j] = s[i][j];
        __syncthreads();

        // ---- O += P @ V ----
#pragma unroll 8
        for (int kv = 0; kv < 64; kv++) {
            float p0 = KP[(tr * 4 + 0) * 65 + kv];
            float p1 = KP[(tr * 4 + 1) * 65 + kv];
            float p2 = KP[(tr * 4 + 2) * 65 + kv];
            float p3 = KP[(tr * 4 + 3) * 65 + kv];
            float v0 = Vs[kv * 65 + tc * 4 + 0];
            float v1 = Vs[kv * 65 + tc * 4 + 1];
            float v2 = Vs[kv * 65 + tc * 4 + 2];
            float v3 = Vs[kv * 65 + tc * 4 + 3];
            acc[0][0] += p0 * v0; acc[0][1] += p0 * v1; acc[0][2] += p0 * v2; acc[0][3] += p0 * v3;
            acc[1][0] += p1 * v0; acc[1][1] += p1 * v1; acc[1][2] += p1 * v2; acc[1][3] += p1 * v3;
            acc[2][0] += p2 * v0; acc[2][1] += p2 * v1; acc[2][2] += p2 * v2; acc[2][3] += p2 * v3;
            acc[3][0] += p3 * v0; acc[3][1] += p3 * v1; acc[3][2] += p3 * v2; acc[3][3] += p3 * v3;
        }
        __syncthreads();
    }

    // ---- epilogue: normalize + write [b, n, h*64 + c] ----
    float* obase = outp + (rowbase + q0) * MDIM + h * DHEAD;
#pragma unroll
    for (int i = 0; i < 4; i++) {
        float inv = 1.0f / l[i];
        float4 o;
        o.x = acc[i][0] * inv;
        o.y = acc[i][1] * inv;
        o.z = acc[i][2] * inv;
        o.w = acc[i][3] * inv;
        *(float4*)(obase + (size_t)(tr * 4 + i) * MDIM + tc * 4) = o;
    }
}

// ---------------- IBPP branch: silu(xr @ w_in + b_in) @ w_out + b_out -----
// one thread per (token, row-of-16); writes into g_cat cols [512, 768)
__global__ __launch_bounds__(256) void ib_kernel(
    const float* __restrict__ x,
    const float* __restrict__ w_in, const float* __restrict__ b_in,
    const float* __restrict__ w_out, const float* __restrict__ b_out,
    float* __restrict__ cat)
{
    __shared__ float wi[16][16], wo[16][16], bi[16], bo[16];
    const int tid = threadIdx.x;
    wi[tid >> 4][tid & 15] = w_in[tid];
    wo[tid >> 4][tid & 15] = w_out[tid];
    if (tid < 16) { bi[tid] = b_in[tid]; bo[tid] = b_out[tid]; }
    __syncthreads();

    const int gid = blockIdx.x * 256 + tid;
    const int token = gid >> 4;
    const int i = gid & 15;

    const float* xr = x + (size_t)token * INDIM + i * 16;
    float xv[16];
#pragma unroll
    for (int k = 0; k < 16; k++) xv[k] = xr[k];

    float t1[16];
#pragma unroll
    for (int j = 0; j < 16; j++) {
        float s = bi[j];
#pragma unroll
        for (int k = 0; k < 16; k++) s += xv[k] * wi[k][j];
        t1[j] = s / (1.0f + __expf(-s));   // silu
    }

    float* o = cat + (size_t)token * CATD + MDIM + i * 16;
#pragma unroll
    for (int j = 0; j < 16; j++) {
        float s = bo[j];
#pragma unroll
        for (int k = 0; k < 16; k++) s += t1[k] * wo[k][j];
        o[j] = s;
    }
}

// ---------------- launch ---------------------------------------------------
extern "C" void kernel_launch(void* const* d_in, const int* in_sizes, int n_in,
                              void* d_out, int out_size)
{
    const float* x       = (const float*)d_in[0];
    const float* w_qkv   = (const float*)d_in[1];
    const float* b_qkv   = (const float*)d_in[2];
    const float* w_in    = (const float*)d_in[3];
    const float* b_in    = (const float*)d_in[4];
    const float* w_out   = (const float*)d_in[5];
    const float* b_out   = (const float*)d_in[6];
    const float* w_merge = (const float*)d_in[7];
    const float* b_merge = (const float*)d_in[8];
    const float* w_proj  = (const float*)d_in[9];
    const float* b_proj  = (const float*)d_in[10];
    float* out = (float*)d_out;

    float *qkv, *attn, *cat;
    cudaGetSymbolAddress((void**)&qkv,  g_qkv);
    cudaGetSymbolAddress((void**)&attn, g_attn);
    cudaGetSymbolAddress((void**)&cat,  g_cat);

    const int attn_smem = 3 * 64 * 65 * (int)sizeof(float);   // 49920 B
    cudaFuncSetAttribute(attn_kernel,
                         cudaFuncAttributeMaxDynamicSharedMemorySize, attn_smem);

    // 1) QKV = x @ w_qkv + b_qkv          [8192,1536] K=256
    gemm_bias<<<dim3(QKV3 / 64, TOKENS / 64), 256>>>(
        x, INDIM, w_qkv, QKV3, b_qkv, qkv, QKV3, TOKENS, QKV3, INDIM);

    // 2) flash attention -> g_attn        [8192,512]
    attn_kernel<<<dim3(NSEQ / 64, NHEADS, 4), 256, attn_smem>>>(qkv, attn);

    // 3) IBPP branch -> g_cat[:, 512:768]
    ib_kernel<<<TOKENS * 16 / 256, 256>>>(x, w_in, b_in, w_out, b_out, cat);

    // 4) merged = attn @ w_merge + b_merge -> g_cat[:, 0:512]
    gemm_bias<<<dim3(MDIM / 64, TOKENS / 64), 256>>>(
        attn, MDIM, w_merge, MDIM, b_merge, cat, CATD, TOKENS, MDIM, MDIM);

    // 5) out = g_cat @ w_proj + b_proj    [8192,512] K=768
    gemm_bias<<<dim3(MDIM / 64, TOKENS / 64), 256>>>(
        cat, CATD, w_proj, MDIM, b_proj, out, MDIM, TOKENS, MDIM, CATD);
}

// round 16
// speedup vs baseline: 1.6860x; 1.6860x over previous
#include <cuda_runtime.h>
#include <cuda_bf16.h>
#include <cstdint>

#define TOKENS 8192
#define INDIM  256
#define MDIM   512
#define QKV3   1536
#define NHEADS 8
#define DHEAD  64
#define NSEQ   2048
#define CATD   768
// logits use exp2: fold softmax scale * log2(e) into Q
#define QLOG2  (0.125f * 1.4426950408889634f)

// ---------------- scratch (device globals; no allocations allowed) --------
__device__ float g_qkv [TOKENS * QKV3];
__device__ float g_attn[TOKENS * MDIM];
__device__ float g_cat [TOKENS * CATD];
__device__ float g_wqkvT [QKV3 * INDIM];  // [1536, 256]
__device__ float g_wmrgT [MDIM * MDIM];   // [512, 512]
__device__ float g_wprjT [MDIM * CATD];   // [512, 768]

// =================== mma.sync helpers (base ISA, compute_103-safe) ========
__device__ __forceinline__ void mma_bf16(float* d, const uint32_t* a, const uint32_t* b) {
    asm volatile(
        "mma.sync.aligned.m16n8k16.row.col.f32.bf16.bf16.f32 "
        "{%0,%1,%2,%3}, {%4,%5,%6,%7}, {%8,%9}, {%0,%1,%2,%3};\n"
        : "+f"(d[0]), "+f"(d[1]), "+f"(d[2]), "+f"(d[3])
        : "r"(a[0]), "r"(a[1]), "r"(a[2]), "r"(a[3]), "r"(b[0]), "r"(b[1]));
}

// pack two floats -> bf16x2; lo_el goes to low 16 bits (smaller k/col index)
__device__ __forceinline__ uint32_t pack2(float lo_el, float hi_el) {
    uint32_t r;
    asm("cvt.rn.bf16x2.f32 %0, %1, %2;" : "=r"(r) : "f"(hi_el), "f"(lo_el));
    return r;
}

__device__ __forceinline__ float bf16_of(float x) {
    return __bfloat162float(__float2bfloat16(x));
}

// split x0,x1 into hi/lo bf16x2 pairs (x0 in low half)
__device__ __forceinline__ void split_pack(float x0, float x1,
                                           uint32_t& hi, uint32_t& lo) {
    float h0 = bf16_of(x0), h1 = bf16_of(x1);
    hi = pack2(h0, h1);
    lo = pack2(x0 - h0, x1 - h1);
}

__device__ __forceinline__ float ex2(float x) {
    float y;
    asm("ex2.approx.ftz.f32 %0, %1;" : "=f"(y) : "f"(x));
    return y;
}

// =================== bf16x3 tensor-core GEMM ==============================
// C[M,N] = A[M,K] @ Bt[N,K]^T + bias.  A pitch = K, Bt pitch = K.
// 128x128 tile, BK=32, 256 threads (8 warps: 2 rows x 4 cols of 64x32).
#define GP 17   // smem pitch in b32 (32 bf16 + 2 pad)

__global__ __launch_bounds__(256) void gemm_bf16x3(
    const float* __restrict__ A, const float* __restrict__ Bt,
    const float* __restrict__ bias, float* __restrict__ C,
    int ldc, int K)
{
    __shared__ uint32_t As_hi[128 * GP], As_lo[128 * GP];
    __shared__ uint32_t Bs_hi[128 * GP], Bs_lo[128 * GP];

    const int tid = threadIdx.x;
    const int wid = tid >> 5, lane = tid & 31;
    const int gid = lane >> 2, tig = lane & 3;
    const int m0 = blockIdx.y * 128, n0 = blockIdx.x * 128;
    const int wrow = (wid & 1) * 64, wcol = (wid >> 1) * 32;

    float acc[4][4][4];
#pragma unroll
    for (int i = 0; i < 4; i++)
#pragma unroll
        for (int j = 0; j < 4; j++)
#pragma unroll
            for (int r = 0; r < 4; r++) acc[i][j][r] = 0.f;

    for (int k0 = 0; k0 < K; k0 += 32) {
        // ---- stage A,Bt chunk with hi/lo split ----
#pragma unroll
        for (int it = 0; it < 4; it++) {
            int idx = tid + it * 256;       // 0..1023
            int r = idx >> 3, c4 = idx & 7; // row 0..127, float4-col 0..7
            int sa = r * GP + c4 * 2;

            float4 va = *(const float4*)(A + (size_t)(m0 + r) * K + k0 + c4 * 4);
            float h0 = bf16_of(va.x), h1 = bf16_of(va.y);
            float h2 = bf16_of(va.z), h3 = bf16_of(va.w);
            As_hi[sa]     = pack2(h0, h1);
            As_hi[sa + 1] = pack2(h2, h3);
            As_lo[sa]     = pack2(va.x - h0, va.y - h1);
            As_lo[sa + 1] = pack2(va.z - h2, va.w - h3);

            float4 vb = *(const float4*)(Bt + (size_t)(n0 + r) * K + k0 + c4 * 4);
            float g0 = bf16_of(vb.x), g1 = bf16_of(vb.y);
            float g2 = bf16_of(vb.z), g3 = bf16_of(vb.w);
            Bs_hi[sa]     = pack2(g0, g1);
            Bs_hi[sa + 1] = pack2(g2, g3);
            Bs_lo[sa]     = pack2(vb.x - g0, vb.y - g1);
            Bs_lo[sa + 1] = pack2(vb.z - g2, vb.w - g3);
        }
        __syncthreads();

#pragma unroll
        for (int kk = 0; kk < 2; kk++) {
            const int kcol = kk * 8 + tig;
            uint32_t ah[4][4], al2[4][4];
#pragma unroll
            for (int mt = 0; mt < 4; mt++) {
                int base = (wrow + mt * 16 + gid) * GP + kcol;
                ah[mt][0]  = As_hi[base];            al2[mt][0] = As_lo[base];
                ah[mt][1]  = As_hi[base + 8 * GP];   al2[mt][1] = As_lo[base + 8 * GP];
                ah[mt][2]  = As_hi[base + 4];        al2[mt][2] = As_lo[base + 4];
                ah[mt][3]  = As_hi[base + 8 * GP + 4]; al2[mt][3] = As_lo[base + 8 * GP + 4];
            }
            uint32_t bh[4][2], bl2[4][2];
#pragma unroll
            for (int nt = 0; nt < 4; nt++) {
                int bb = (wcol + nt * 8 + gid) * GP + kcol;
                bh[nt][0] = Bs_hi[bb]; bh[nt][1] = Bs_hi[bb + 4];
                bl2[nt][0] = Bs_lo[bb]; bl2[nt][1] = Bs_lo[bb + 4];
            }
#pragma unroll
            for (int mt = 0; mt < 4; mt++)
#pragma unroll
                for (int nt = 0; nt < 4; nt++) {
                    mma_bf16(acc[mt][nt], ah[mt], bh[nt]);
                    mma_bf16(acc[mt][nt], ah[mt], bl2[nt]);
                    mma_bf16(acc[mt][nt], al2[mt], bh[nt]);
                }
        }
        __syncthreads();
    }

    // ---- epilogue ----
#pragma unroll
    for (int mt = 0; mt < 4; mt++) {
        int r0 = m0 + wrow + mt * 16 + gid;
#pragma unroll
        for (int nt = 0; nt < 4; nt++) {
            int c = n0 + wcol + nt * 8 + tig * 2;
            float b0 = bias[c], b1 = bias[c + 1];
            *(float2*)&C[(size_t)r0 * ldc + c] =
                make_float2(acc[mt][nt][0] + b0, acc[mt][nt][1] + b1);
            *(float2*)&C[(size_t)(r0 + 8) * ldc + c] =
                make_float2(acc[mt][nt][2] + b0, acc[mt][nt][3] + b1);
        }
    }
}

// ---------------- weight transpose: out[c][r] = in[r][c] -------------------
__global__ __launch_bounds__(256) void transpose_k(
    const float* __restrict__ in, float* __restrict__ out, int R, int C)
{
    __shared__ float t[32][33];
    const int bx = blockIdx.x * 32, by = blockIdx.y * 32;
    const int x = threadIdx.x & 31, y = (threadIdx.x >> 5) * 4;
#pragma unroll
    for (int i = 0; i < 4; i++)
        t[y + i][x] = in[(size_t)(by + y + i) * C + bx + x];
    __syncthreads();
#pragma unroll
    for (int i = 0; i < 4; i++)
        out[(size_t)(bx + y + i) * R + by + x] = t[x][y + i];
}

// =================== flash attention, bf16x3 mma ==========================
// block = 64 q-rows x 1 head x 1 batch, 128 threads (warp owns 16 q-rows).
// K smem [kv=64][d=64] (b32 packs d,d+1); V smem TRANSPOSED [d=64][kv=64].
#define AP 33   // smem pitch in b32 (64 bf16 + 2 pad)

__global__ __launch_bounds__(128) void attn_mma(
    const float* __restrict__ qkv, float* __restrict__ outp)
{
    __shared__ uint32_t Ks_hi[64 * AP], Ks_lo[64 * AP];
    __shared__ uint32_t Vs_hi[64 * AP], Vs_lo[64 * AP];

    const int tid = threadIdx.x;
    const int wid = tid >> 5, lane = tid & 31;
    const int gid = lane >> 2, tig = lane & 3;
    const int q0 = blockIdx.x * 64;
    const int h  = blockIdx.y;
    const int b  = blockIdx.z;
    const size_t rowbase = (size_t)b * NSEQ;

    // ---- Q fragments (scaled, split hi/lo), loaded once ----
    uint32_t qh[4][4], ql[4][4];
    {
        const float* qbase = qkv + (rowbase + q0 + wid * 16) * QKV3 + h * DHEAD;
#pragma unroll
        for (int kk = 0; kk < 4; kk++) {
            int col = kk * 16 + tig * 2;
#pragma unroll
            for (int half = 0; half < 2; half++) {
                float2 v0 = *(const float2*)(qbase + (size_t)gid * QKV3 + col + half * 8);
                float2 v1 = *(const float2*)(qbase + (size_t)(gid + 8) * QKV3 + col + half * 8);
                v0.x *= QLOG2; v0.y *= QLOG2; v1.x *= QLOG2; v1.y *= QLOG2;
                split_pack(v0.x, v0.y, qh[kk][half * 2],     ql[kk][half * 2]);
                split_pack(v1.x, v1.y, qh[kk][half * 2 + 1], ql[kk][half * 2 + 1]);
            }
        }
    }

    float o[8][4];
#pragma unroll
    for (int i = 0; i < 8; i++)
#pragma unroll
        for (int j = 0; j < 4; j++) o[i][j] = 0.f;
    float mr0 = -1e30f, mr1 = -1e30f, l0 = 0.f, l1 = 0.f;

    for (int t = 0; t < NSEQ; t += 64) {
        const float* kp = qkv + (rowbase + t) * QKV3 + MDIM + h * DHEAD;
        const float* vp = qkv + (rowbase + t) * QKV3 + 2 * MDIM + h * DHEAD;
        __nv_bfloat16* vh = (__nv_bfloat16*)Vs_hi;
        __nv_bfloat16* vl = (__nv_bfloat16*)Vs_lo;
#pragma unroll
        for (int i = 0; i < 8; i++) {
            int idx = tid + i * 128;
            int r = idx >> 4, c4 = idx & 15;   // kv row, float4-col (d)
            float4 kv4 = *(const float4*)(kp + (size_t)r * QKV3 + c4 * 4);
            float h0 = bf16_of(kv4.x), h1 = bf16_of(kv4.y);
            float h2 = bf16_of(kv4.z), h3 = bf16_of(kv4.w);
            int sa = r * AP + c4 * 2;
            Ks_hi[sa]     = pack2(h0, h1);
            Ks_hi[sa + 1] = pack2(h2, h3);
            Ks_lo[sa]     = pack2(kv4.x - h0, kv4.y - h1);
            Ks_lo[sa + 1] = pack2(kv4.z - h2, kv4.w - h3);

            float4 vv = *(const float4*)(vp + (size_t)r * QKV3 + c4 * 4);
#pragma unroll
            for (int j = 0; j < 4; j++) {
                float x = (&vv.x)[j];
                __nv_bfloat16 hb = __float2bfloat16(x);
                vh[(c4 * 4 + j) * (2 * AP) + r] = hb;
                vl[(c4 * 4 + j) * (2 * AP) + r] =
                    __float2bfloat16(x - __bfloat162float(hb));
            }
        }
        __syncthreads();

        // ---- S = (Q*scale) @ K^T, bf16x3 ----
        float sc[8][4];
#pragma unroll
        for (int i = 0; i < 8; i++)
#pragma unroll
            for (int j = 0; j < 4; j++) sc[i][j] = 0.f;

#pragma unroll
        for (int kk = 0; kk < 4; kk++) {
#pragma unroll
            for (int nt = 0; nt < 8; nt++) {
                int bb = (nt * 8 + gid) * AP + kk * 8 + tig;
                uint32_t bh[2] = {Ks_hi[bb], Ks_hi[bb + 4]};
                uint32_t bl[2] = {Ks_lo[bb], Ks_lo[bb + 4]};
                mma_bf16(sc[nt], qh[kk], bh);
                mma_bf16(sc[nt], qh[kk], bl);
                mma_bf16(sc[nt], ql[kk], bh);
            }
        }

        // ---- online softmax (log2 domain), rows gid and gid+8 ----
        float t0 = -1e30f, t1 = -1e30f;
#pragma unroll
        for (int nt = 0; nt < 8; nt++) {
            t0 = fmaxf(t0, fmaxf(sc[nt][0], sc[nt][1]));
            t1 = fmaxf(t1, fmaxf(sc[nt][2], sc[nt][3]));
        }
        t0 = fmaxf(t0, __shfl_xor_sync(0xffffffffu, t0, 1));
        t0 = fmaxf(t0, __shfl_xor_sync(0xffffffffu, t0, 2));
        t1 = fmaxf(t1, __shfl_xor_sync(0xffffffffu, t1, 1));
        t1 = fmaxf(t1, __shfl_xor_sync(0xffffffffu, t1, 2));
        float mn0 = fmaxf(mr0, t0), mn1 = fmaxf(mr1, t1);
        float al0 = ex2(mr0 - mn0), al1 = ex2(mr1 - mn1);
        mr0 = mn0; mr1 = mn1;
        float rs0 = 0.f, rs1 = 0.f;
#pragma unroll
        for (int nt = 0; nt < 8; nt++) {
            sc[nt][0] = ex2(sc[nt][0] - mn0);
            sc[nt][1] = ex2(sc[nt][1] - mn0);
            sc[nt][2] = ex2(sc[nt][2] - mn1);
            sc[nt][3] = ex2(sc[nt][3] - mn1);
            rs0 += sc[nt][0] + sc[nt][1];
            rs1 += sc[nt][2] + sc[nt][3];
        }
        rs0 += __shfl_xor_sync(0xffffffffu, rs0, 1);
        rs0 += __shfl_xor_sync(0xffffffffu, rs0, 2);
        rs1 += __shfl_xor_sync(0xffffffffu, rs1, 1);
        rs1 += __shfl_xor_sync(0xffffffffu, rs1, 2);
        l0 = l0 * al0 + rs0;
        l1 = l1 * al1 + rs1;
#pragma unroll
        for (int dn = 0; dn < 8; dn++) {
            o[dn][0] *= al0; o[dn][1] *= al0;
            o[dn][2] *= al1; o[dn][3] *= al1;
        }

        // ---- O += P @ V  (P re-packed in-register as A-fragments) ----
#pragma unroll
        for (int kk = 0; kk < 4; kk++) {
            uint32_t ph[4], pl[4];
            split_pack(sc[2 * kk][0],     sc[2 * kk][1],     ph[0], pl[0]);
            split_pack(sc[2 * kk][2],     sc[2 * kk][3],     ph[1], pl[1]);
            split_pack(sc[2 * kk + 1][0], sc[2 * kk + 1][1], ph[2], pl[2]);
            split_pack(sc[2 * kk + 1][2], sc[2 * kk + 1][3], ph[3], pl[3]);
#pragma unroll
            for (int dn = 0; dn < 8; dn++) {
                int bb = (dn * 8 + gid) * AP + kk * 8 + tig;
                uint32_t vhf[2] = {Vs_hi[bb], Vs_hi[bb + 4]};
                uint32_t vlf[2] = {Vs_lo[bb], Vs_lo[bb + 4]};
                mma_bf16(o[dn], ph, vhf);
                mma_bf16(o[dn], ph, vlf);
                mma_bf16(o[dn], pl, vhf);
            }
        }
        __syncthreads();
    }

    // ---- epilogue ----
    float inv0 = 1.f / l0, inv1 = 1.f / l1;
    float* ob = outp + (rowbase + q0 + wid * 16) * MDIM + h * DHEAD;
#pragma unroll
    for (int dn = 0; dn < 8; dn++) {
        *(float2*)(ob + (size_t)gid * MDIM + dn * 8 + tig * 2) =
            make_float2(o[dn][0] * inv0, o[dn][1] * inv0);
        *(float2*)(ob + (size_t)(gid + 8) * MDIM + dn * 8 + tig * 2) =
            make_float2(o[dn][2] * inv1, o[dn][3] * inv1);
    }
}

// ---------------- IBPP branch ---------------------------------------------
__global__ __launch_bounds__(256) void ib_kernel(
    const float* __restrict__ x,
    const float* __restrict__ w_in, const float* __restrict__ b_in,
    const float* __restrict__ w_out, const float* __restrict__ b_out,
    float* __restrict__ cat)
{
    __shared__ float wi[16][16], wo[16][16], bi[16], bo[16];
    const int tid = threadIdx.x;
    wi[tid >> 4][tid & 15] = w_in[tid];
    wo[tid >> 4][tid & 15] = w_out[tid];
    if (tid < 16) { bi[tid] = b_in[tid]; bo[tid] = b_out[tid]; }
    __syncthreads();

    const int gid = blockIdx.x * 256 + tid;
    const int token = gid >> 4;
    const int i = gid & 15;

    const float* xr = x + (size_t)token * INDIM + i * 16;
    float xv[16];
#pragma unroll
    for (int k = 0; k < 16; k++) xv[k] = xr[k];

    float t1[16];
#pragma unroll
    for (int j = 0; j < 16; j++) {
        float s = bi[j];
#pragma unroll
        for (int k = 0; k < 16; k++) s += xv[k] * wi[k][j];
        t1[j] = s / (1.0f + __expf(-s));
    }

    float* o = cat + (size_t)token * CATD + MDIM + i * 16;
#pragma unroll
    for (int j = 0; j < 16; j++) {
        float s = bo[j];
#pragma unroll
        for (int k = 0; k < 16; k++) s += t1[k] * wo[k][j];
        o[j] = s;
    }
}

// ---------------- launch ---------------------------------------------------
extern "C" void kernel_launch(void* const* d_in, const int* in_sizes, int n_in,
                              void* d_out, int out_size)
{
    const float* x       = (const float*)d_in[0];
    const float* w_qkv   = (const float*)d_in[1];
    const float* b_qkv   = (const float*)d_in[2];
    const float* w_in    = (const float*)d_in[3];
    const float* b_in    = (const float*)d_in[4];
    const float* w_out   = (const float*)d_in[5];
    const float* b_out   = (const float*)d_in[6];
    const float* w_merge = (const float*)d_in[7];
    const float* b_merge = (const float*)d_in[8];
    const float* w_proj  = (const float*)d_in[9];
    const float* b_proj  = (const float*)d_in[10];
    float* out = (float*)d_out;

    float *qkv, *attn, *cat, *wqkvT, *wmrgT, *wprjT;
    cudaGetSymbolAddress((void**)&qkv,   g_qkv);
    cudaGetSymbolAddress((void**)&attn,  g_attn);
    cudaGetSymbolAddress((void**)&cat,   g_cat);
    cudaGetSymbolAddress((void**)&wqkvT, g_wqkvT);
    cudaGetSymbolAddress((void**)&wmrgT, g_wmrgT);
    cudaGetSymbolAddress((void**)&wprjT, g_wprjT);

    // 0) transpose weights to [N, K]
    transpose_k<<<dim3(QKV3 / 32, INDIM / 32), 256>>>(w_qkv,   wqkvT, INDIM, QKV3);
    transpose_k<<<dim3(MDIM / 32, MDIM / 32), 256>>>(w_merge, wmrgT, MDIM, MDIM);
    transpose_k<<<dim3(MDIM / 32, CATD / 32), 256>>>(w_proj,  wprjT, CATD, MDIM);

    // 1) QKV = x @ w_qkv + b_qkv            [8192,1536], K=256
    gemm_bf16x3<<<dim3(QKV3 / 128, TOKENS / 128), 256>>>(
        x, wqkvT, b_qkv, qkv, QKV3, INDIM);

    // 2) flash attention -> g_attn          [8192,512]
    attn_mma<<<dim3(NSEQ / 64, NHEADS, 4), 128>>>(qkv, attn);

    // 3) IBPP branch -> g_cat[:, 512:768]
    ib_kernel<<<TOKENS * 16 / 256, 256>>>(x, w_in, b_in, w_out, b_out, cat);

    // 4) merged -> g_cat[:, 0:512]          [8192,512], K=512
    gemm_bf16x3<<<dim3(MDIM / 128, TOKENS / 128), 256>>>(
        attn, wmrgT, b_merge, cat, CATD, MDIM);

    // 5) out = g_cat @ w_proj + b_proj      [8192,512], K=768
    gemm_bf16x3<<<dim3(MDIM / 128, TOKENS / 128), 256>>>(
        cat, wprjT, b_proj, out, MDIM, CATD);
}

// round 17
// speedup vs baseline: 2.2312x; 1.3234x over previous
#include <cuda_runtime.h>
#include <cuda_bf16.h>
#include <cstdint>

#define TOKENS 8192
#define INDIM  256
#define MDIM   512
#define QKV3   1536
#define NHEADS 8
#define DHEAD  64
#define NSEQ   2048
#define CATD   768
// softmax in exp2 domain: scale * log2(e)
#define QLOG2  (0.125f * 1.4426950408889634f)

// ---------------- scratch (device globals; no allocations) ----------------
__device__ __nv_bfloat16 g_xh  [TOKENS * INDIM];
__device__ __nv_bfloat16 g_xl  [TOKENS * INDIM];
__device__ __nv_bfloat16 g_qkvh[TOKENS * QKV3];
__device__ __nv_bfloat16 g_qkvl[TOKENS * QKV3];
__device__ __nv_bfloat16 g_atth[TOKENS * MDIM];
__device__ __nv_bfloat16 g_attl[TOKENS * MDIM];
__device__ __nv_bfloat16 g_cath[TOKENS * CATD];
__device__ __nv_bfloat16 g_catl[TOKENS * CATD];
__device__ __nv_bfloat16 g_wqkvh[QKV3 * INDIM], g_wqkvl[QKV3 * INDIM];
__device__ __nv_bfloat16 g_wmrgh[MDIM * MDIM],  g_wmrgl[MDIM * MDIM];
__device__ __nv_bfloat16 g_wprjh[MDIM * CATD],  g_wprjl[MDIM * CATD];

// =================== helpers (base ISA, compute_103-safe) =================
__device__ __forceinline__ uint32_t smem_u32(const void* p) {
    uint32_t a;
    asm("{ .reg .u64 t; cvta.to.shared.u64 t, %1; cvt.u32.u64 %0, t; }"
        : "=r"(a) : "l"(p));
    return a;
}
__device__ __forceinline__ void cp16(uint32_t dst, const void* src) {
    asm volatile("cp.async.cg.shared.global [%0], [%1], 16;"
                 :: "r"(dst), "l"(src) : "memory");
}
#define CP_COMMIT() asm volatile("cp.async.commit_group;" ::: "memory")
#define CP_WAIT0()  asm volatile("cp.async.wait_group 0;" ::: "memory")

__device__ __forceinline__ void mma_bf16(float* d, const uint32_t* a, const uint32_t* b) {
    asm volatile(
        "mma.sync.aligned.m16n8k16.row.col.f32.bf16.bf16.f32 "
        "{%0,%1,%2,%3}, {%4,%5,%6,%7}, {%8,%9}, {%0,%1,%2,%3};\n"
        : "+f"(d[0]), "+f"(d[1]), "+f"(d[2]), "+f"(d[3])
        : "r"(a[0]), "r"(a[1]), "r"(a[2]), "r"(a[3]), "r"(b[0]), "r"(b[1]));
}
__device__ __forceinline__ uint32_t pack2(float lo_el, float hi_el) {
    uint32_t r;
    asm("cvt.rn.bf16x2.f32 %0, %1, %2;" : "=r"(r) : "f"(hi_el), "f"(lo_el));
    return r;
}
__device__ __forceinline__ float bf16_of(float x) {
    return __bfloat162float(__float2bfloat16(x));
}
__device__ __forceinline__ void split_pack(float x0, float x1,
                                           uint32_t& hi, uint32_t& lo) {
    float h0 = bf16_of(x0), h1 = bf16_of(x1);
    hi = pack2(h0, h1);
    lo = pack2(x0 - h0, x1 - h1);
}
__device__ __forceinline__ float ex2(float x) {
    float y;
    asm("ex2.approx.ftz.f32 %0, %1;" : "=f"(y) : "f"(x));
    return y;
}
// store split pair (x0,x1) at &h[i], &l[i] (i even)
__device__ __forceinline__ void store_split2(__nv_bfloat16* h, __nv_bfloat16* l,
                                             size_t i, float x0, float x1) {
    uint32_t hv, lv;
    split_pack(x0, x1, hv, lv);
    *(uint32_t*)(h + i) = hv;
    *(uint32_t*)(l + i) = lv;
}

// =================== bf16x3 GEMM (pre-split inputs, cp.async 2-stage) =====
// C = A @ Bt^T + bias.  A_h/l: [M,K] bf16 pitch K.  Bt_h/l: [N,K] bf16 pitch K.
// 128x128 tile, BK=32, 256 threads (8 warps: 2x4 of 64x32).
// smem row pitch = 80 B (4x16B data + 16B pad). b32 pitch = 20.
#define GB   10240                 // bytes per array per buffer
#define GBUF (4 * GB)
#define GEMM_SMEM (2 * GBUF)       // 81920

struct GemmPtrs {
    const __nv_bfloat16 *Ah, *Al, *Bh, *Bl;
    const float* bias;
    float* Cf;                     // fp32 output (or null)
    __nv_bfloat16 *Ch, *Cl;        // split output (or null)
};

__global__ __launch_bounds__(256) void gemm_bf16x3(
    GemmPtrs p, int ldc, int K)
{
    extern __shared__ char smraw[];
    const uint32_t sb = smem_u32(smraw);

    const int tid = threadIdx.x;
    const int wid = tid >> 5, lane = tid & 31;
    const int gid = lane >> 2, tig = lane & 3;
    const int m0 = blockIdx.y * 128, n0 = blockIdx.x * 128;
    const int wrow = (wid & 1) * 64, wcol = (wid >> 1) * 32;

    const int s_r = tid >> 2, s_c = tid & 3;           // staging row / 16B col
    const uint32_t s_off = (uint32_t)(s_r * 80 + s_c * 16);

    float acc[4][4][4];
#pragma unroll
    for (int i = 0; i < 4; i++)
#pragma unroll
        for (int j = 0; j < 4; j++)
#pragma unroll
            for (int r = 0; r < 4; r++) acc[i][j][r] = 0.f;

    const int KC = K / 32;

    // ---- staging: 2 rows per thread per array (rows s_r, s_r+64) ----
#define STAGE(k0, buf) do {                                                    \
    uint32_t b0 = sb + (buf) * GBUF;                                           \
    _Pragma("unroll")                                                          \
    for (int it = 0; it < 2; it++) {                                           \
        int r = s_r + it * 64;                                                 \
        uint32_t so = (uint32_t)(r * 80 + s_c * 16);                           \
        size_t ga = (size_t)(m0 + r) * K + (k0) + s_c * 8;                     \
        size_t gb = (size_t)(n0 + r) * K + (k0) + s_c * 8;                     \
        cp16(b0 + 0 * GB + so, p.Ah + ga);                                     \
        cp16(b0 + 1 * GB + so, p.Al + ga);                                     \
        cp16(b0 + 2 * GB + so, p.Bh + gb);                                     \
        cp16(b0 + 3 * GB + so, p.Bl + gb);                                     \
    }                                                                          \
    CP_COMMIT();                                                               \
} while (0)

    STAGE(0, 0);

    for (int kc = 0; kc < KC; kc++) {
        CP_WAIT0();
        __syncthreads();
        if (kc + 1 < KC) STAGE((kc + 1) * 32, (kc + 1) & 1);

        const uint32_t* S = (const uint32_t*)(smraw + (kc & 1) * GBUF);
        const uint32_t* Ahs = S;
        const uint32_t* Als = S + GB / 4;
        const uint32_t* Bhs = S + 2 * (GB / 4);
        const uint32_t* Bls = S + 3 * (GB / 4);

#pragma unroll
        for (int kk = 0; kk < 2; kk++) {
            const int kcol = kk * 8 + tig;
            uint32_t ah[4][4], al2[4][4];
#pragma unroll
            for (int mt = 0; mt < 4; mt++) {
                int base = (wrow + mt * 16 + gid) * 20 + kcol;
                ah[mt][0]  = Ahs[base];            al2[mt][0] = Als[base];
                ah[mt][1]  = Ahs[base + 160];      al2[mt][1] = Als[base + 160];
                ah[mt][2]  = Ahs[base + 4];        al2[mt][2] = Als[base + 4];
                ah[mt][3]  = Ahs[base + 164];      al2[mt][3] = Als[base + 164];
            }
            uint32_t bh[4][2], bl2[4][2];
#pragma unroll
            for (int nt = 0; nt < 4; nt++) {
                int bb = (wcol + nt * 8 + gid) * 20 + kcol;
                bh[nt][0] = Bhs[bb]; bh[nt][1] = Bhs[bb + 4];
                bl2[nt][0] = Bls[bb]; bl2[nt][1] = Bls[bb + 4];
            }
#pragma unroll
            for (int mt = 0; mt < 4; mt++)
#pragma unroll
                for (int nt = 0; nt < 4; nt++) {
                    mma_bf16(acc[mt][nt], ah[mt], bh[nt]);
                    mma_bf16(acc[mt][nt], ah[mt], bl2[nt]);
                    mma_bf16(acc[mt][nt], al2[mt], bh[nt]);
                }
        }
        __syncthreads();
    }

    // ---- epilogue ----
#pragma unroll
    for (int mt = 0; mt < 4; mt++) {
        int r0 = m0 + wrow + mt * 16 + gid;
#pragma unroll
        for (int nt = 0; nt < 4; nt++) {
            int c = n0 + wcol + nt * 8 + tig * 2;
            float b0 = p.bias[c], b1 = p.bias[c + 1];
            float v00 = acc[mt][nt][0] + b0, v01 = acc[mt][nt][1] + b1;
            float v10 = acc[mt][nt][2] + b0, v11 = acc[mt][nt][3] + b1;
            if (p.Cf) {
                *(float2*)&p.Cf[(size_t)r0 * ldc + c]       = make_float2(v00, v01);
                *(float2*)&p.Cf[(size_t)(r0 + 8) * ldc + c] = make_float2(v10, v11);
            } else {
                store_split2(p.Ch, p.Cl, (size_t)r0 * ldc + c, v00, v01);
                store_split2(p.Ch, p.Cl, (size_t)(r0 + 8) * ldc + c, v10, v11);
            }
        }
    }
}

// ---------------- input split: x fp32 -> xh/xl bf16 ------------------------
__global__ __launch_bounds__(256) void split_x(
    const float* __restrict__ x, __nv_bfloat16* __restrict__ xh,
    __nv_bfloat16* __restrict__ xl)
{
    size_t i = ((size_t)blockIdx.x * 256 + threadIdx.x) * 4;
    float4 v = *(const float4*)(x + i);
    store_split2(xh, xl, i,     v.x, v.y);
    store_split2(xh, xl, i + 2, v.z, v.w);
}

// ---------------- weight transpose + split: [R,C] fp32 -> [C,R] bf16 h/l ---
__global__ __launch_bounds__(256) void transpose_split(
    const float* __restrict__ in, __nv_bfloat16* __restrict__ oh,
    __nv_bfloat16* __restrict__ ol, int R, int C)
{
    __shared__ float t[32][33];
    const int bx = blockIdx.x * 32, by = blockIdx.y * 32;
    const int x = threadIdx.x & 31, y = (threadIdx.x >> 5) * 4;
#pragma unroll
    for (int i = 0; i < 4; i++)
        t[y + i][x] = in[(size_t)(by + y + i) * C + bx + x];
    __syncthreads();
#pragma unroll
    for (int i = 0; i < 4; i++) {
        float v = t[x][y + i];
        float h = bf16_of(v);
        size_t o = (size_t)(bx + y + i) * R + by + x;
        oh[o] = __float2bfloat16(h);
        ol[o] = __float2bfloat16(v - h);
    }
}

// =================== flash attention, bf16x3, pre-split QKV ===============
// block = 128 q-rows x head x batch; 256 threads; warp owns 16 q-rows.
// K smem [kv=64][d=64]; V smem transposed [d=64][kv=64]. pitch 36 b32 (144B).
#define APX 36

__global__ __launch_bounds__(256) void attn_mma(
    const __nv_bfloat16* __restrict__ qk_h, const __nv_bfloat16* __restrict__ qk_l,
    __nv_bfloat16* __restrict__ oh_g, __nv_bfloat16* __restrict__ ol_g)
{
    __shared__ uint32_t Ks_hi[64 * APX], Ks_lo[64 * APX];
    __shared__ uint32_t Vs_hi[64 * APX], Vs_lo[64 * APX];

    const int tid = threadIdx.x;
    const int wid = tid >> 5, lane = tid & 31;
    const int gid = lane >> 2, tig = lane & 3;
    const int q0 = blockIdx.x * 128;
    const int h  = blockIdx.y;
    const int b  = blockIdx.z;
    const size_t rowbase = (size_t)b * NSEQ;

    // ---- Q fragments (unscaled; scale applied to logits) ----
    uint32_t qh[4][4], ql[4][4];
    {
        const __nv_bfloat16* qb = qk_h + (rowbase + q0 + wid * 16) * QKV3 + h * DHEAD;
        const __nv_bfloat16* qlb = qk_l + (rowbase + q0 + wid * 16) * QKV3 + h * DHEAD;
#pragma unroll
        for (int kk = 0; kk < 4; kk++) {
            int col = kk * 16 + tig * 2;
            qh[kk][0] = *(const uint32_t*)(qb  + (size_t)gid * QKV3 + col);
            qh[kk][1] = *(const uint32_t*)(qb  + (size_t)(gid + 8) * QKV3 + col);
            qh[kk][2] = *(const uint32_t*)(qb  + (size_t)gid * QKV3 + col + 8);
            qh[kk][3] = *(const uint32_t*)(qb  + (size_t)(gid + 8) * QKV3 + col + 8);
            ql[kk][0] = *(const uint32_t*)(qlb + (size_t)gid * QKV3 + col);
            ql[kk][1] = *(const uint32_t*)(qlb + (size_t)(gid + 8) * QKV3 + col);
            ql[kk][2] = *(const uint32_t*)(qlb + (size_t)gid * QKV3 + col + 8);
            ql[kk][3] = *(const uint32_t*)(qlb + (size_t)(gid + 8) * QKV3 + col + 8);
        }
    }

    float o[8][4];
#pragma unroll
    for (int i = 0; i < 8; i++)
#pragma unroll
        for (int j = 0; j < 4; j++) o[i][j] = 0.f;
    float mr0 = -1e30f, mr1 = -1e30f, l0 = 0.f, l1 = 0.f;

    const uint32_t kh_base = smem_u32(Ks_hi);
    const uint32_t kl_base = smem_u32(Ks_lo);
    __nv_bfloat16* vh16 = (__nv_bfloat16*)Vs_hi;
    __nv_bfloat16* vl16 = (__nv_bfloat16*)Vs_lo;

    for (int t = 0; t < NSEQ; t += 64) {
        // ---- K tiles via cp.async ----
        {
            int r = tid >> 2, c = tid & 3;                  // 64 rows x 2x16B halves
#pragma unroll
            for (int half = 0; half < 2; half++) {
                uint32_t so = (uint32_t)(r * 144 + (c + half * 4) * 16);
                size_t g = (rowbase + t + r) * QKV3 + MDIM + h * DHEAD + (c + half * 4) * 8;
                cp16(kh_base + so, qk_h + g);
                cp16(kl_base + so, qk_l + g);
            }
            CP_COMMIT();
        }
        // ---- V tiles: manual transpose staging (bf16 source) ----
#pragma unroll
        for (int it = 0; it < 2; it++) {
            int idx = tid + it * 256;
            int kv = idx & 63, c = (idx >> 6) * 8;
            size_t g = (rowbase + t + kv) * QKV3 + 2 * MDIM + h * DHEAD + c;
            uint4 hv = *(const uint4*)(qk_h + g);
            uint4 lv = *(const uint4*)(qk_l + g);
            const __nv_bfloat16* hp = (const __nv_bfloat16*)&hv;
            const __nv_bfloat16* lp = (const __nv_bfloat16*)&lv;
#pragma unroll
            for (int j = 0; j < 8; j++) {
                vh16[(c + j) * 72 + kv] = hp[j];
                vl16[(c + j) * 72 + kv] = lp[j];
            }
        }
        CP_WAIT0();
        __syncthreads();

        // ---- S = Q @ K^T ----
        float sc[8][4];
#pragma unroll
        for (int i = 0; i < 8; i++)
#pragma unroll
            for (int j = 0; j < 4; j++) sc[i][j] = 0.f;

#pragma unroll
        for (int kk = 0; kk < 4; kk++) {
            const int kcol = kk * 8 + tig;
#pragma unroll
            for (int nt = 0; nt < 8; nt++) {
                int bb = (nt * 8 + gid) * APX + kcol;
                uint32_t bh[2] = {Ks_hi[bb], Ks_hi[bb + 4]};
                uint32_t bl[2] = {Ks_lo[bb], Ks_lo[bb + 4]};
                mma_bf16(sc[nt], qh[kk], bh);
                mma_bf16(sc[nt], qh[kk], bl);
                mma_bf16(sc[nt], ql[kk], bh);
            }
        }

        // ---- online softmax (exp2 domain) ----
        float t0 = -1e30f, t1 = -1e30f;
#pragma unroll
        for (int nt = 0; nt < 8; nt++) {
#pragma unroll
            for (int j = 0; j < 4; j++) sc[nt][j] *= QLOG2;
            t0 = fmaxf(t0, fmaxf(sc[nt][0], sc[nt][1]));
            t1 = fmaxf(t1, fmaxf(sc[nt][2], sc[nt][3]));
        }
        t0 = fmaxf(t0, __shfl_xor_sync(0xffffffffu, t0, 1));
        t0 = fmaxf(t0, __shfl_xor_sync(0xffffffffu, t0, 2));
        t1 = fmaxf(t1, __shfl_xor_sync(0xffffffffu, t1, 1));
        t1 = fmaxf(t1, __shfl_xor_sync(0xffffffffu, t1, 2));
        float mn0 = fmaxf(mr0, t0), mn1 = fmaxf(mr1, t1);
        float al0 = ex2(mr0 - mn0), al1 = ex2(mr1 - mn1);
        mr0 = mn0; mr1 = mn1;
        float rs0 = 0.f, rs1 = 0.f;
#pragma unroll
        for (int nt = 0; nt < 8; nt++) {
            sc[nt][0] = ex2(sc[nt][0] - mn0);
            sc[nt][1] = ex2(sc[nt][1] - mn0);
            sc[nt][2] = ex2(sc[nt][2] - mn1);
            sc[nt][3] = ex2(sc[nt][3] - mn1);
            rs0 += sc[nt][0] + sc[nt][1];
            rs1 += sc[nt][2] + sc[nt][3];
        }
        rs0 += __shfl_xor_sync(0xffffffffu, rs0, 1);
        rs0 += __shfl_xor_sync(0xffffffffu, rs0, 2);
        rs1 += __shfl_xor_sync(0xffffffffu, rs1, 1);
        rs1 += __shfl_xor_sync(0xffffffffu, rs1, 2);
        l0 = l0 * al0 + rs0;
        l1 = l1 * al1 + rs1;
#pragma unroll
        for (int dn = 0; dn < 8; dn++) {
            o[dn][0] *= al0; o[dn][1] *= al0;
            o[dn][2] *= al1; o[dn][3] *= al1;
        }

        // ---- O += P @ V ----
#pragma unroll
        for (int kk = 0; kk < 4; kk++) {
            uint32_t ph[4], pl[4];
            split_pack(sc[2 * kk][0],     sc[2 * kk][1],     ph[0], pl[0]);
            split_pack(sc[2 * kk][2],     sc[2 * kk][3],     ph[1], pl[1]);
            split_pack(sc[2 * kk + 1][0], sc[2 * kk + 1][1], ph[2], pl[2]);
            split_pack(sc[2 * kk + 1][2], sc[2 * kk + 1][3], ph[3], pl[3]);
            const int kcol = kk * 8 + tig;
#pragma unroll
            for (int dn = 0; dn < 8; dn++) {
                int bb = (dn * 8 + gid) * APX + kcol;
                uint32_t vhf[2] = {Vs_hi[bb], Vs_hi[bb + 4]};
                uint32_t vlf[2] = {Vs_lo[bb], Vs_lo[bb + 4]};
                mma_bf16(o[dn], ph, vhf);
                mma_bf16(o[dn], ph, vlf);
                mma_bf16(o[dn], pl, vhf);
            }
        }
        __syncthreads();
    }

    // ---- epilogue: split bf16 output ----
    float inv0 = 1.f / l0, inv1 = 1.f / l1;
    size_t ob = (rowbase + q0 + wid * 16) * MDIM + h * DHEAD;
#pragma unroll
    for (int dn = 0; dn < 8; dn++) {
        int c = dn * 8 + tig * 2;
        store_split2(oh_g, ol_g, ob + (size_t)gid * MDIM + c,
                     o[dn][0] * inv0, o[dn][1] * inv0);
        store_split2(oh_g, ol_g, ob + (size_t)(gid + 8) * MDIM + c,
                     o[dn][2] * inv1, o[dn][3] * inv1);
    }
}

// ---------------- IBPP branch (fp32 math, split output) --------------------
__global__ __launch_bounds__(256) void ib_kernel(
    const float* __restrict__ x,
    const float* __restrict__ w_in, const float* __restrict__ b_in,
    const float* __restrict__ w_out, const float* __restrict__ b_out,
    __nv_bfloat16* __restrict__ ch, __nv_bfloat16* __restrict__ cl)
{
    __shared__ float wi[16][16], wo[16][16], bi[16], bo[16];
    const int tid = threadIdx.x;
    wi[tid >> 4][tid & 15] = w_in[tid];
    wo[tid >> 4][tid & 15] = w_out[tid];
    if (tid < 16) { bi[tid] = b_in[tid]; bo[tid] = b_out[tid]; }
    __syncthreads();

    const int gid = blockIdx.x * 256 + tid;
    const int token = gid >> 4;
    const int i = gid & 15;

    const float* xr = x + (size_t)token * INDIM + i * 16;
    float xv[16];
#pragma unroll
    for (int k = 0; k < 16; k++) xv[k] = xr[k];

    float t1[16];
#pragma unroll
    for (int j = 0; j < 16; j++) {
        float s = bi[j];
#pragma unroll
        for (int k = 0; k < 16; k++) s += xv[k] * wi[k][j];
        t1[j] = s / (1.0f + __expf(-s));
    }

    size_t ob = (size_t)token * CATD + MDIM + i * 16;
#pragma unroll
    for (int j = 0; j < 16; j += 2) {
        float s0 = bo[j], s1 = bo[j + 1];
#pragma unroll
        for (int k = 0; k < 16; k++) {
            s0 += t1[k] * wo[k][j];
            s1 += t1[k] * wo[k][j + 1];
        }
        store_split2(ch, cl, ob + j, s0, s1);
    }
}

// ---------------- launch ---------------------------------------------------
extern "C" void kernel_launch(void* const* d_in, const int* in_sizes, int n_in,
                              void* d_out, int out_size)
{
    const float* x       = (const float*)d_in[0];
    const float* w_qkv   = (const float*)d_in[1];
    const float* b_qkv   = (const float*)d_in[2];
    const float* w_in    = (const float*)d_in[3];
    const float* b_in    = (const float*)d_in[4];
    const float* w_out   = (const float*)d_in[5];
    const float* b_out   = (const float*)d_in[6];
    const float* w_merge = (const float*)d_in[7];
    const float* b_merge = (const float*)d_in[8];
    const float* w_proj  = (const float*)d_in[9];
    const float* b_proj  = (const float*)d_in[10];
    float* out = (float*)d_out;

    __nv_bfloat16 *xh, *xl, *qkvh, *qkvl, *atth, *attl, *cath, *catl;
    __nv_bfloat16 *wqh, *wql, *wmh, *wml, *wph, *wpl;
    cudaGetSymbolAddress((void**)&xh,   g_xh);
    cudaGetSymbolAddress((void**)&xl,   g_xl);
    cudaGetSymbolAddress((void**)&qkvh, g_qkvh);
    cudaGetSymbolAddress((void**)&qkvl, g_qkvl);
    cudaGetSymbolAddress((void**)&atth, g_atth);
    cudaGetSymbolAddress((void**)&attl, g_attl);
    cudaGetSymbolAddress((void**)&cath, g_cath);
    cudaGetSymbolAddress((void**)&catl, g_catl);
    cudaGetSymbolAddress((void**)&wqh,  g_wqkvh);
    cudaGetSymbolAddress((void**)&wql,  g_wqkvl);
    cudaGetSymbolAddress((void**)&wmh,  g_wmrgh);
    cudaGetSymbolAddress((void**)&wml,  g_wmrgl);
    cudaGetSymbolAddress((void**)&wph,  g_wprjh);
    cudaGetSymbolAddress((void**)&wpl,  g_wprjl);

    cudaFuncSetAttribute(gemm_bf16x3,
                         cudaFuncAttributeMaxDynamicSharedMemorySize, GEMM_SMEM);

    // 0) pre-split inputs + weights
    split_x<<<TOKENS * INDIM / 1024, 256>>>(x, xh, xl);
    transpose_split<<<dim3(QKV3 / 32, INDIM / 32), 256>>>(w_qkv,   wqh, wql, INDIM, QKV3);
    transpose_split<<<dim3(MDIM / 32, MDIM / 32), 256>>>(w_merge, wmh, wml, MDIM, MDIM);
    transpose_split<<<dim3(MDIM / 32, CATD / 32), 256>>>(w_proj,  wph, wpl, CATD, MDIM);

    // 1) QKV = x @ w_qkv + b_qkv -> split qkv     [8192,1536], K=256
    {
        GemmPtrs p{xh, xl, wqh, wql, b_qkv, nullptr, qkvh, qkvl};
        gemm_bf16x3<<<dim3(QKV3 / 128, TOKENS / 128), 256, GEMM_SMEM>>>(p, QKV3, INDIM);
    }

    // 2) flash attention -> split attn            [8192,512]
    attn_mma<<<dim3(NSEQ / 128, NHEADS, 4), 256>>>(qkvh, qkvl, atth, attl);

    // 3) IBPP -> split cat[:, 512:768]
    ib_kernel<<<TOKENS * 16 / 256, 256>>>(x, w_in, b_in, w_out, b_out, cath, catl);

    // 4) merge -> split cat[:, 0:512]             [8192,512], K=512
    {
        GemmPtrs p{atth, attl, wmh, wml, b_merge, nullptr, cath, catl};
        gemm_bf16x3<<<dim3(MDIM / 128, TOKENS / 128), 256, GEMM_SMEM>>>(p, CATD, MDIM);
    }

    // 5) out = cat @ w_proj + b_proj (fp32)       [8192,512], K=768
    {
        GemmPtrs p{cath, catl, wph, wpl, b_proj, out, nullptr, nullptr};
        gemm_bf16x3<<<dim3(MDIM / 128, TOKENS / 128), 256, GEMM_SMEM>>>(p, MDIM, CATD);
    }
}